// round 4
// baseline (speedup 1.0000x reference)
#include <cuda_runtime.h>

// Prediction_65189013618796
// prob: [B=64, 2N=2048] f32. start = prob[:, :N], end = prob[:, N:].
// band 0 <= j - i <= 15. Inputs uniform[0,1) => non-negative, so:
//   start_position[b,i] = start[b,i] * max(end[b, i..min(i+15,N-1)])
//   end_position[b,j]   = end[b,j]   * max(start[b, max(j-15,0)..j])
// One thread = one float4 output group, one direction. Blocks 0..63 forward,
// 64..127 backward. Fast path (no clamps) for interior groups; clamped path
// only for boundary warps (edge replication is max-neutral: the clamped
// window always contains the edge element).

#define NB 64
#define NN 1024
#define NG (NN / 4)

__device__ __forceinline__ float max4(float4 v) {
    return fmaxf(fmaxf(v.x, v.y), fmaxf(v.z, v.w));
}

// forward: out[m] = start[4g+m] * max(end[4g+m .. 4g+m+15])
template <bool CLAMP>
__device__ __forceinline__ float4 fwd_group(const float4* __restrict__ e4,
                                            const float4* __restrict__ s4, int g) {
    float4 E0, E1, E2, E3, E4v;
    if (CLAMP) {
        #define LDE(dst, gg) { int _g = (gg); float4 _v = e4[_g > NG-1 ? NG-1 : _g]; \
                               if (_g > NG-1) { _v.x = _v.w; _v.y = _v.w; _v.z = _v.w; } dst = _v; }
        LDE(E0, g) LDE(E1, g+1) LDE(E2, g+2) LDE(E3, g+3) LDE(E4v, g+4)
        #undef LDE
    } else {
        E0 = e4[g]; E1 = e4[g+1]; E2 = e4[g+2]; E3 = e4[g+3]; E4v = e4[g+4];
    }
    float4 sv = s4[g];
    float M123 = fmaxf(max4(E1), fmaxf(max4(E2), max4(E3)));
    float t3 = E0.w, t2 = fmaxf(E0.z, t3), t1 = fmaxf(E0.y, t2), t0 = fmaxf(E0.x, t1);
    float p0 = E4v.x, p1 = fmaxf(p0, E4v.y), p2 = fmaxf(p1, E4v.z);
    return make_float4(sv.x * fmaxf(t0, M123),
                       sv.y * fmaxf(t1, fmaxf(M123, p0)),
                       sv.z * fmaxf(t2, fmaxf(M123, p1)),
                       sv.w * fmaxf(t3, fmaxf(M123, p2)));
}

// backward: out[m] = end[4g+m] * max(start[4g+m-15 .. 4g+m])
template <bool CLAMP>
__device__ __forceinline__ float4 bwd_group(const float4* __restrict__ s4,
                                            const float4* __restrict__ e4, int g) {
    float4 S0, S1, S2, S3, S4v;  // S0 = own group g, S1..S4v = groups g-1..g-4
    if (CLAMP) {
        #define LDS_(dst, gg) { int _g = (gg); float4 _v = s4[_g < 0 ? 0 : _g]; \
                                if (_g < 0) { _v.y = _v.x; _v.z = _v.x; _v.w = _v.x; } dst = _v; }
        LDS_(S0, g) LDS_(S1, g-1) LDS_(S2, g-2) LDS_(S3, g-3) LDS_(S4v, g-4)
        #undef LDS_
    } else {
        S0 = s4[g]; S1 = s4[g-1]; S2 = s4[g-2]; S3 = s4[g-3]; S4v = s4[g-4];
    }
    float4 ev = e4[g];
    float M123 = fmaxf(max4(S1), fmaxf(max4(S2), max4(S3)));
    float q0 = S0.x, q1 = fmaxf(q0, S0.y), q2 = fmaxf(q1, S0.z), q3 = fmaxf(q2, S0.w);
    float u3 = S4v.w, u2 = fmaxf(S4v.z, u3), u1 = fmaxf(S4v.y, u2);
    return make_float4(ev.x * fmaxf(q0, fmaxf(M123, u1)),
                       ev.y * fmaxf(q1, fmaxf(M123, u2)),
                       ev.z * fmaxf(q2, fmaxf(M123, u3)),
                       ev.w * fmaxf(q3, M123));
}

__global__ __launch_bounds__(256, 8)
void banded_span_kernel(const float* __restrict__ prob, float* __restrict__ out) {
    const int idx = (blockIdx.x & 63) * 256 + threadIdx.x;  // 0..16383
    const int b = idx >> 8;
    const int g = idx & (NG - 1);

    const float4* row4 = reinterpret_cast<const float4*>(prob + (size_t)b * 2 * NN);
    float4* o4 = reinterpret_cast<float4*>(out);

    if (blockIdx.x < 64) {
        const float4* e4 = row4 + NG;
        float4 r = (g <= NG - 5) ? fwd_group<false>(e4, row4, g)
                                 : fwd_group<true>(e4, row4, g);
        o4[(size_t)b * NG + g] = r;
    } else {
        const float4* e4 = row4 + NG;
        float4 r = (g >= 4) ? bwd_group<false>(row4, e4, g)
                            : bwd_group<true>(row4, e4, g);
        o4[(size_t)NB * NG + (size_t)b * NG + g] = r;
    }
}

extern "C" void kernel_launch(void* const* d_in, const int* in_sizes, int n_in,
                              void* d_out, int out_size) {
    const float* prob = (const float*)d_in[0];
    float* out = (float*)d_out;
    banded_span_kernel<<<128, 256>>>(prob, out);
}

// round 5
// speedup vs baseline: 1.0047x; 1.0047x over previous
#include <cuda_runtime.h>

// Prediction_65189013618796
// prob: [B=64, 2N=2048] float32. start = prob[:, :N], end = prob[:, N:].
// band 0 <= j - i <= 15. Inputs uniform[0,1) => non-negative, so:
//   start_position[b,i] = start[b,i] * max(end[b, i..min(i+15,N-1)])
//   end_position[b,j]   = end[b,j]   * max(start[b, max(j-15,0)..j])
//
// 32768 threads, each produces ONE float4 output group for ONE direction.
// Blocks 0..31 -> forward (start_position), 32..63 -> backward. Uniform per
// CTA, no divergence. Edge padding replicates end[N-1] / start[0]
// (max-neutral: the clamped window always contains that element).
// grid=64 x block=512: single wave, minimal CTA dispatch ramp.

#define NB   64
#define NN   1024
#define NG   (NN / 4)     // 256 float4 groups per row

__global__ __launch_bounds__(512, 4)
void banded_span_kernel(const float* __restrict__ prob, float* __restrict__ out) {
    const int idx = (blockIdx.x & 31) * 512 + threadIdx.x;  // 0..16383
    const int b = idx >> 8;                                 // row 0..63
    const int g = idx & (NG - 1);                           // group 0..255

    const float4* row4 = reinterpret_cast<const float4*>(prob + (size_t)b * 2 * NN);
    float4* o4 = reinterpret_cast<float4*>(out);

    if (blockIdx.x < 32) {
        // ---- forward: start_position[b, 4g..4g+3] ----
        const float4* e4 = row4 + NG;
        float e[20];
        #pragma unroll
        for (int k = 0; k < 5; ++k) {
            int gg = g + k;
            float4 v = e4[gg > NG - 1 ? NG - 1 : gg];
            if (gg > NG - 1) { v.x = v.w; v.y = v.w; v.z = v.w; }
            e[4 * k + 0] = v.x; e[4 * k + 1] = v.y;
            e[4 * k + 2] = v.z; e[4 * k + 3] = v.w;
        }
        float4 sv = row4[g];  // start point values

        // shared core max(e[3..15]), tree-shaped
        float c01 = fmaxf(e[3], e[4]),   c23 = fmaxf(e[5], e[6]);
        float c45 = fmaxf(e[7], e[8]),   c67 = fmaxf(e[9], e[10]);
        float c89 = fmaxf(e[11], e[12]), cab = fmaxf(e[13], e[14]);
        float ce = fmaxf(fmaxf(fmaxf(c01, c23), fmaxf(c45, c67)),
                         fmaxf(fmaxf(c89, cab), e[15]));
        float fe0 = fmaxf(fmaxf(ce, e[0]),  fmaxf(e[1],  e[2]));
        float fe1 = fmaxf(fmaxf(ce, e[1]),  fmaxf(e[2],  e[16]));
        float fe2 = fmaxf(fmaxf(ce, e[2]),  fmaxf(e[16], e[17]));
        float fe3 = fmaxf(fmaxf(ce, e[16]), fmaxf(e[17], e[18]));

        o4[(size_t)b * NG + g] =
            make_float4(sv.x * fe0, sv.y * fe1, sv.z * fe2, sv.w * fe3);
    } else {
        // ---- backward: end_position[b, 4g..4g+3] ----
        float s[20];
        #pragma unroll
        for (int k = 0; k < 5; ++k) {
            int gg = g - 4 + k;
            float4 v = row4[gg < 0 ? 0 : gg];
            if (gg < 0) { v.y = v.x; v.z = v.x; v.w = v.x; }
            s[4 * k + 0] = v.x; s[4 * k + 1] = v.y;
            s[4 * k + 2] = v.z; s[4 * k + 3] = v.w;
        }
        float4 ev = row4[NG + g];  // end point values

        // shared core max(s[4..16])
        float c01 = fmaxf(s[4], s[5]),   c23 = fmaxf(s[6], s[7]);
        float c45 = fmaxf(s[8], s[9]),   c67 = fmaxf(s[10], s[11]);
        float c89 = fmaxf(s[12], s[13]), cab = fmaxf(s[14], s[15]);
        float cs = fmaxf(fmaxf(fmaxf(c01, c23), fmaxf(c45, c67)),
                         fmaxf(fmaxf(c89, cab), s[16]));
        float ms0 = fmaxf(fmaxf(cs, s[1]),  fmaxf(s[2],  s[3]));
        float ms1 = fmaxf(fmaxf(cs, s[2]),  fmaxf(s[3],  s[17]));
        float ms2 = fmaxf(fmaxf(cs, s[3]),  fmaxf(s[17], s[18]));
        float ms3 = fmaxf(fmaxf(cs, s[17]), fmaxf(s[18], s[19]));

        o4[(size_t)NB * NG + (size_t)b * NG + g] =
            make_float4(ev.x * ms0, ev.y * ms1, ev.z * ms2, ev.w * ms3);
    }
}

extern "C" void kernel_launch(void* const* d_in, const int* in_sizes, int n_in,
                              void* d_out, int out_size) {
    const float* prob = (const float*)d_in[0];
    float* out = (float*)d_out;
    banded_span_kernel<<<64, 512>>>(prob, out);
}